// round 8
// baseline (speedup 1.0000x reference)
#include <cuda_runtime.h>
#include <cuda_fp16.h>
#include <cstdint>

#define NTOK   4096
#define DMODEL 1024
#define NEXP   8
#define TOPK   2
#define HEXP   704
#define HSH    1408

#define BM 64
#define BN 64
#define BK 16
#define NTHREADS 256

// ---------------- scratch (device globals; no allocation allowed) ----------
__device__ int   g_cnt[NEXP];
__device__ int   g_off[NEXP + 1];
__device__ int   g_cur[NEXP];
__device__ int   g_topi[NTOK * TOPK];
__device__ float g_topw[NTOK * TOPK];
__device__ int   g_tok[NTOK * TOPK];
__device__ float g_gate[NTOK * TOPK];
__device__ float g_hid_r[NTOK * TOPK * HEXP];   // routed SwiGLU hidden
__device__ float g_hid_s[NTOK * HSH];           // shared-expert hidden

// ---------------- helpers ----------------------------------------------------
__device__ __forceinline__ float silu_f(float z) {
    return z / (1.f + __expf(-z));
}
__device__ __forceinline__ uint32_t f2h2(float lo, float hi) {
    __half2 h = __floats2half2_rn(lo, hi);
    return *reinterpret_cast<uint32_t*>(&h);
}
__device__ __forceinline__ void mma_f16(float* c, const uint32_t* a,
                                        uint32_t b0, uint32_t b1) {
    asm volatile(
        "mma.sync.aligned.m16n8k16.row.col.f32.f16.f16.f32 "
        "{%0,%1,%2,%3}, {%4,%5,%6,%7}, {%8,%9}, {%0,%1,%2,%3};\n"
        : "+f"(c[0]), "+f"(c[1]), "+f"(c[2]), "+f"(c[3])
        : "r"(a[0]), "r"(a[1]), "r"(a[2]), "r"(a[3]), "r"(b0), "r"(b1));
}

// ---------------- tiny setup kernels ---------------------------------------
__global__ void zero_kernel() {
    int t = threadIdx.x;
    if (t < NEXP) { g_cnt[t] = 0; g_cur[t] = 0; }
}
__global__ void scan_kernel() {
    int acc = 0;
    g_off[0] = 0;
    for (int e = 0; e < NEXP; e++) { acc += g_cnt[e]; g_off[e + 1] = acc; }
}
__global__ void router_kernel(const float* __restrict__ x,
                              const float* __restrict__ Wg) {
    int gw   = (blockIdx.x * blockDim.x + threadIdx.x) >> 5;
    int lane = threadIdx.x & 31;
    if (gw >= NTOK) return;
    const float* xr = x + (size_t)gw * DMODEL;

    float acc[NEXP];
#pragma unroll
    for (int e = 0; e < NEXP; e++) acc[e] = 0.f;
    for (int k = lane; k < DMODEL; k += 32) {
        float xv = xr[k];
#pragma unroll
        for (int e = 0; e < NEXP; e++) acc[e] += xv * Wg[e * DMODEL + k];
    }
#pragma unroll
    for (int e = 0; e < NEXP; e++) {
#pragma unroll
        for (int o = 16; o > 0; o >>= 1)
            acc[e] += __shfl_xor_sync(0xffffffffu, acc[e], o);
    }
    if (lane == 0) {
        float m = acc[0];
#pragma unroll
        for (int e = 1; e < NEXP; e++) m = fmaxf(m, acc[e]);
        float p[NEXP], s = 0.f;
#pragma unroll
        for (int e = 0; e < NEXP; e++) { p[e] = expf(acc[e] - m); s += p[e]; }
        float inv = 1.f / s;
#pragma unroll
        for (int e = 0; e < NEXP; e++) p[e] *= inv;

        int i0 = 0; float v0 = p[0];
#pragma unroll
        for (int e = 1; e < NEXP; e++) if (p[e] > v0) { v0 = p[e]; i0 = e; }
        int i1 = (i0 == 0) ? 1 : 0; float v1 = p[i1];
#pragma unroll
        for (int e = 0; e < NEXP; e++)
            if (e != i0 && p[e] > v1) { v1 = p[e]; i1 = e; }

        float sw = v0 + v1 + 1e-20f;
        g_topi[gw * 2] = i0;  g_topi[gw * 2 + 1] = i1;
        g_topw[gw * 2] = v0 / sw;  g_topw[gw * 2 + 1] = v1 / sw;
        atomicAdd(&g_cnt[i0], 1);
        atomicAdd(&g_cnt[i1], 1);
    }
}
__global__ void fill_kernel() {
    int n = blockIdx.x * blockDim.x + threadIdx.x;
    if (n >= NTOK) return;
#pragma unroll
    for (int s = 0; s < TOPK; s++) {
        int e   = g_topi[n * 2 + s];
        int pos = atomicAdd(&g_cur[e], 1);
        int idx = g_off[e] + pos;
        g_tok[idx]  = n;
        g_gate[idx] = g_topw[n * 2 + s];
    }
}

// ---------------- shared-memory unions --------------------------------------
struct S1F { float As[BK][BM + 4]; float Bs1[BK][BN]; float Bs3[BK][BN]; };
struct S1H { uint32_t As[BM][12]; uint32_t Bs[2][BK / 2][68]; };
union  S1U { S1F f; S1H h; };

struct S2F { float As[BK][BM + 4]; float Bs[BK][BN]; };
struct S2H { uint32_t As[BM][12]; uint32_t Bs[BK / 2][68]; };
union  S2U { S2F f; S2H h; };

// ============ GEMM1 unified: hid = silu(A@W1)*(A@W3) ========================
// blockIdx.x < nh -> fp16 HMMA path (tensor pipe); else fp32 FFMA path.
template<bool ROUTED>
__global__ __launch_bounds__(NTHREADS)
void gemm1_u(const float* __restrict__ x,
             const float* __restrict__ W1g,
             const float* __restrict__ W3g,
             float* __restrict__ hid, int H, int nh) {
    int e = 0, base = 0, ne = NTOK;
    if (ROUTED) { e = blockIdx.z; base = g_off[e]; ne = g_off[e + 1] - base; }
    int m0 = blockIdx.y * BM;
    if (m0 >= ne) return;
    int n0 = blockIdx.x * BN;

    const float* W1 = W1g + (ROUTED ? (size_t)e * DMODEL * H : 0) + n0;
    const float* W3 = W3g + (ROUTED ? (size_t)e * DMODEL * H : 0) + n0;

    __shared__ S1U u;
    __shared__ int stok[BM];

    int tid = threadIdx.x;
    if (tid < BM)
        stok[tid] = ROUTED ? ((m0 + tid < ne) ? g_tok[base + m0 + tid] : -1)
                           : (m0 + tid);
    __syncthreads();

    if ((int)blockIdx.x < nh) {
        // ---------------- fp16 HMMA path (round-7 verified) -----------------
        int ar = tid >> 2, acw = (tid & 3) * 2;
        int tk = stok[ar];
        bool aok = (tk >= 0);
        const float* Arow = x + (size_t)(aok ? tk : 0) * DMODEL;

        int bmat = tid >> 7;
        int bt   = tid & 127;
        int bj   = bt >> 4;
        int bn   = (bt & 15) * 4;
        const float* Bsrc = (bmat ? W3 : W1) + bn;

        float4 av  = aok ? *(const float4*)(Arow + acw * 2) : make_float4(0, 0, 0, 0);
        float4 bv0 = *(const float4*)(Bsrc + (size_t)(2 * bj)     * H);
        float4 bv1 = *(const float4*)(Bsrc + (size_t)(2 * bj + 1) * H);

        int lane = tid & 31, wid = tid >> 5;
        int mw = (wid & 1) * 32, nw = (wid >> 1) * 16;
        int g = lane >> 2, tq = lane & 3;

        float acc1[2][2][4], acc3[2][2][4];
#pragma unroll
        for (int i = 0; i < 2; i++)
#pragma unroll
            for (int j = 0; j < 2; j++)
#pragma unroll
                for (int k = 0; k < 4; k++) { acc1[i][j][k] = 0.f; acc3[i][j][k] = 0.f; }

        for (int kk = 0; kk < DMODEL; kk += BK) {
            u.h.As[ar][acw]     = f2h2(av.x, av.y);
            u.h.As[ar][acw + 1] = f2h2(av.z, av.w);
            u.h.Bs[bmat][bj][bn + 0] = f2h2(bv0.x, bv1.x);
            u.h.Bs[bmat][bj][bn + 1] = f2h2(bv0.y, bv1.y);
            u.h.Bs[bmat][bj][bn + 2] = f2h2(bv0.z, bv1.z);
            u.h.Bs[bmat][bj][bn + 3] = f2h2(bv0.w, bv1.w);
            __syncthreads();

            int kn = kk + BK;
            if (kn < DMODEL) {
                if (aok) av = *(const float4*)(Arow + kn + acw * 2);
                bv0 = *(const float4*)(Bsrc + (size_t)(kn + 2 * bj)     * H);
                bv1 = *(const float4*)(Bsrc + (size_t)(kn + 2 * bj + 1) * H);
            }

            uint32_t a[2][4];
#pragma unroll
            for (int mt = 0; mt < 2; mt++) {
                int r = mw + mt * 16 + g;
                a[mt][0] = u.h.As[r][tq];
                a[mt][1] = u.h.As[r + 8][tq];
                a[mt][2] = u.h.As[r][tq + 4];
                a[mt][3] = u.h.As[r + 8][tq + 4];
            }
#pragma unroll
            for (int nt = 0; nt < 2; nt++) {
                int c = nw + nt * 8 + g;
                uint32_t p0 = u.h.Bs[0][tq][c];
                uint32_t p1 = u.h.Bs[0][tq + 4][c];
                uint32_t q0 = u.h.Bs[1][tq][c];
                uint32_t q1 = u.h.Bs[1][tq + 4][c];
#pragma unroll
                for (int mt = 0; mt < 2; mt++) {
                    mma_f16(acc1[mt][nt], a[mt], p0, p1);
                    mma_f16(acc3[mt][nt], a[mt], q0, q1);
                }
            }
            __syncthreads();
        }

#pragma unroll
        for (int mt = 0; mt < 2; mt++) {
#pragma unroll
            for (int h = 0; h < 2; h++) {
                int r = mw + mt * 16 + g + h * 8;
                if (!ROUTED || (m0 + r < ne)) {
                    size_t rowoff = (size_t)(base + m0 + r) * H + n0;
#pragma unroll
                    for (int nt = 0; nt < 2; nt++) {
                        int col = nw + nt * 8 + 2 * tq;
                        float2 v;
                        v.x = silu_f(acc1[mt][nt][2 * h])     * acc3[mt][nt][2 * h];
                        v.y = silu_f(acc1[mt][nt][2 * h + 1]) * acc3[mt][nt][2 * h + 1];
                        *(float2*)&hid[rowoff + col] = v;
                    }
                }
            }
        }
    } else {
        // ---------------- fp32 FFMA path (round-1 verified) -----------------
        int ar = tid >> 2, ac = (tid & 3) * 4;
        int br = tid >> 4, bc = (tid & 15) * 4;
        int tk = stok[ar];
        bool aok = (tk >= 0);
        const float* Arow = x + (size_t)(aok ? tk : 0) * DMODEL;

        float4 av  = aok ? *(const float4*)(Arow + ac) : make_float4(0, 0, 0, 0);
        float4 b1v = *(const float4*)(W1 + (size_t)br * H + bc);
        float4 b3v = *(const float4*)(W3 + (size_t)br * H + bc);

        int tm0 = (tid >> 4) * 4, tn0 = (tid & 15) * 4;
        float acc1[4][4] = {}, acc3[4][4] = {};

        for (int kk = 0; kk < DMODEL; kk += BK) {
            u.f.As[ac + 0][ar] = av.x; u.f.As[ac + 1][ar] = av.y;
            u.f.As[ac + 2][ar] = av.z; u.f.As[ac + 3][ar] = av.w;
            *(float4*)&u.f.Bs1[br][bc] = b1v;
            *(float4*)&u.f.Bs3[br][bc] = b3v;
            __syncthreads();
            int kn = kk + BK;
            if (kn < DMODEL) {
                if (aok) av = *(const float4*)(Arow + kn + ac);
                b1v = *(const float4*)(W1 + (size_t)(kn + br) * H + bc);
                b3v = *(const float4*)(W3 + (size_t)(kn + br) * H + bc);
            }
#pragma unroll
            for (int k = 0; k < BK; k++) {
                float4 a  = *(const float4*)&u.f.As[k][tm0];
                float4 b1 = *(const float4*)&u.f.Bs1[k][tn0];
                float4 b3 = *(const float4*)&u.f.Bs3[k][tn0];
                float aa[4]  = { a.x, a.y, a.z, a.w };
                float bb1[4] = { b1.x, b1.y, b1.z, b1.w };
                float bb3[4] = { b3.x, b3.y, b3.z, b3.w };
#pragma unroll
                for (int i = 0; i < 4; i++)
#pragma unroll
                    for (int j = 0; j < 4; j++) {
                        acc1[i][j] = fmaf(aa[i], bb1[j], acc1[i][j]);
                        acc3[i][j] = fmaf(aa[i], bb3[j], acc3[i][j]);
                    }
            }
            __syncthreads();
        }
#pragma unroll
        for (int i = 0; i < 4; i++) {
            int r = tm0 + i;
            if (!ROUTED || (m0 + r < ne)) {
                float4 hv;
                hv.x = silu_f(acc1[i][0]) * acc3[i][0];
                hv.y = silu_f(acc1[i][1]) * acc3[i][1];
                hv.z = silu_f(acc1[i][2]) * acc3[i][2];
                hv.w = silu_f(acc1[i][3]) * acc3[i][3];
                *(float4*)&hid[(size_t)(base + m0 + r) * H + n0 + tn0] = hv;
            }
        }
    }
}

// ============ GEMM2 unified: out (+)= [gate *] (hid @ W2) ===================
template<bool ROUTED>
__global__ __launch_bounds__(NTHREADS)
void gemm2_u(const float* __restrict__ hidg,
             const float* __restrict__ W2g,
             float* __restrict__ out, int K, int nh) {
    int e = 0, base = 0, ne = NTOK;
    if (ROUTED) { e = blockIdx.z; base = g_off[e]; ne = g_off[e + 1] - base; }
    int m0 = blockIdx.y * BM;
    if (m0 >= ne) return;
    int n0 = blockIdx.x * BN;

    const float* W2 = W2g + (ROUTED ? (size_t)e * K * DMODEL : 0) + n0;

    __shared__ S2U u;
    __shared__ int   stok[BM];
    __shared__ float sgate[BM];

    int tid = threadIdx.x;
    if (ROUTED) {
        if (tid < BM) {
            bool v = (m0 + tid < ne);
            stok[tid]  = v ? g_tok[base + m0 + tid] : 0;
            sgate[tid] = v ? g_gate[base + m0 + tid] : 0.f;
        }
        __syncthreads();
    }

    if ((int)blockIdx.x < nh) {
        // ---------------- fp16 HMMA path ------------------------------------
        int ar = tid >> 2, acw = (tid & 3) * 2;
        bool aok = (m0 + ar < ne);
        const float* Arow = hidg + (size_t)(base + m0 + (aok ? ar : 0)) * K;
        int bj = (tid & 127) >> 4;
        int bn = (tid & 15) * 4;
        bool bload = (tid < 128);

        float4 av  = aok ? *(const float4*)(Arow + acw * 2) : make_float4(0, 0, 0, 0);
        float4 bv0 = make_float4(0, 0, 0, 0), bv1 = make_float4(0, 0, 0, 0);
        if (bload) {
            bv0 = *(const float4*)(W2 + (size_t)(2 * bj)     * DMODEL + bn);
            bv1 = *(const float4*)(W2 + (size_t)(2 * bj + 1) * DMODEL + bn);
        }

        int lane = tid & 31, wid = tid >> 5;
        int mw = (wid & 1) * 32, nw = (wid >> 1) * 16;
        int g = lane >> 2, tq = lane & 3;

        float acc[2][2][4];
#pragma unroll
        for (int i = 0; i < 2; i++)
#pragma unroll
            for (int j = 0; j < 2; j++)
#pragma unroll
                for (int k = 0; k < 4; k++) acc[i][j][k] = 0.f;

        for (int kk = 0; kk < K; kk += BK) {
            u.h.As[ar][acw]     = f2h2(av.x, av.y);
            u.h.As[ar][acw + 1] = f2h2(av.z, av.w);
            if (bload) {
                u.h.Bs[bj][bn + 0] = f2h2(bv0.x, bv1.x);
                u.h.Bs[bj][bn + 1] = f2h2(bv0.y, bv1.y);
                u.h.Bs[bj][bn + 2] = f2h2(bv0.z, bv1.z);
                u.h.Bs[bj][bn + 3] = f2h2(bv0.w, bv1.w);
            }
            __syncthreads();

            int kn = kk + BK;
            if (kn < K) {
                if (aok) av = *(const float4*)(Arow + kn + acw * 2);
                if (bload) {
                    bv0 = *(const float4*)(W2 + (size_t)(kn + 2 * bj)     * DMODEL + bn);
                    bv1 = *(const float4*)(W2 + (size_t)(kn + 2 * bj + 1) * DMODEL + bn);
                }
            }

            uint32_t a[2][4];
#pragma unroll
            for (int mt = 0; mt < 2; mt++) {
                int r = mw + mt * 16 + g;
                a[mt][0] = u.h.As[r][tq];
                a[mt][1] = u.h.As[r + 8][tq];
                a[mt][2] = u.h.As[r][tq + 4];
                a[mt][3] = u.h.As[r + 8][tq + 4];
            }
#pragma unroll
            for (int nt = 0; nt < 2; nt++) {
                int c = nw + nt * 8 + g;
                uint32_t p0 = u.h.Bs[tq][c];
                uint32_t p1 = u.h.Bs[tq + 4][c];
#pragma unroll
                for (int mt = 0; mt < 2; mt++)
                    mma_f16(acc[mt][nt], a[mt], p0, p1);
            }
            __syncthreads();
        }

#pragma unroll
        for (int mt = 0; mt < 2; mt++) {
#pragma unroll
            for (int h = 0; h < 2; h++) {
                int r = mw + mt * 16 + g + h * 8;
                if (ROUTED) {
                    if (m0 + r < ne) {
                        int   tk = stok[r];
                        float w  = sgate[r];
                        float* op = out + (size_t)tk * DMODEL + n0;
#pragma unroll
                        for (int nt = 0; nt < 2; nt++) {
                            int col = nw + nt * 8 + 2 * tq;
                            atomicAdd(op + col,     w * acc[mt][nt][2 * h]);
                            atomicAdd(op + col + 1, w * acc[mt][nt][2 * h + 1]);
                        }
                    }
                } else {
                    size_t rowoff = (size_t)(m0 + r) * DMODEL + n0;
#pragma unroll
                    for (int nt = 0; nt < 2; nt++) {
                        int col = nw + nt * 8 + 2 * tq;
                        float2 v;
                        v.x = acc[mt][nt][2 * h];
                        v.y = acc[mt][nt][2 * h + 1];
                        *(float2*)&out[rowoff + col] = v;
                    }
                }
            }
        }
    } else {
        // ---------------- fp32 FFMA path ------------------------------------
        int ar = tid >> 2, ac = (tid & 3) * 4;
        int br = tid >> 4, bc = (tid & 15) * 4;
        bool aok = (m0 + ar < ne);
        const float* Arow = hidg + (size_t)(base + m0 + (aok ? ar : 0)) * K;

        float4 av = aok ? *(const float4*)(Arow + ac) : make_float4(0, 0, 0, 0);
        float4 bv = *(const float4*)(W2 + (size_t)br * DMODEL + bc);

        int tm0 = (tid >> 4) * 4, tn0 = (tid & 15) * 4;
        float acc[4][4] = {};

        for (int kk = 0; kk < K; kk += BK) {
            u.f.As[ac + 0][ar] = av.x; u.f.As[ac + 1][ar] = av.y;
            u.f.As[ac + 2][ar] = av.z; u.f.As[ac + 3][ar] = av.w;
            *(float4*)&u.f.Bs[br][bc] = bv;
            __syncthreads();
            int kn = kk + BK;
            if (kn < K) {
                if (aok) av = *(const float4*)(Arow + kn + ac);
                bv = *(const float4*)(W2 + (size_t)(kn + br) * DMODEL + bc);
            }
#pragma unroll
            for (int k = 0; k < BK; k++) {
                float4 a = *(const float4*)&u.f.As[k][tm0];
                float4 b = *(const float4*)&u.f.Bs[k][tn0];
                float aa[4] = { a.x, a.y, a.z, a.w };
                float bb[4] = { b.x, b.y, b.z, b.w };
#pragma unroll
                for (int i = 0; i < 4; i++)
#pragma unroll
                    for (int j = 0; j < 4; j++)
                        acc[i][j] = fmaf(aa[i], bb[j], acc[i][j]);
            }
            __syncthreads();
        }
#pragma unroll
        for (int i = 0; i < 4; i++) {
            int r = tm0 + i;
            if (ROUTED) {
                if (m0 + r < ne) {
                    int   tk = stok[r];
                    float w  = sgate[r];
                    float* op = out + (size_t)tk * DMODEL + n0 + tn0;
#pragma unroll
                    for (int j = 0; j < 4; j++)
                        atomicAdd(op + j, w * acc[i][j]);
                }
            } else {
                float4 ov = make_float4(acc[i][0], acc[i][1], acc[i][2], acc[i][3]);
                *(float4*)&out[(size_t)(m0 + r) * DMODEL + n0 + tn0] = ov;
            }
        }
    }
}

// ---------------- launch -----------------------------------------------------
extern "C" void kernel_launch(void* const* d_in, const int* in_sizes, int n_in,
                              void* d_out, int out_size) {
    const float* x   = (const float*)d_in[0];
    const float* Wg  = (const float*)d_in[1];
    const float* W1  = (const float*)d_in[2];
    const float* W3  = (const float*)d_in[3];
    const float* W2  = (const float*)d_in[4];
    const float* Ws1 = (const float*)d_in[5];
    const float* Ws3 = (const float*)d_in[6];
    const float* Ws2 = (const float*)d_in[7];
    float* out = (float*)d_out;

    zero_kernel<<<1, 32>>>();
    router_kernel<<<NTOK / 8, 256>>>(x, Wg);
    scan_kernel<<<1, 1>>>();
    fill_kernel<<<NTOK / 256, 256>>>();

    // ~28% of column-blocks on the tensor pipe, rest on the fma pipe
    gemm1_u<false><<<dim3(HSH / BN, NTOK / BM), NTHREADS>>>(x, Ws1, Ws3, g_hid_s, HSH, 6);
    gemm2_u<false><<<dim3(DMODEL / BN, NTOK / BM), NTHREADS>>>(g_hid_s, Ws2, out, HSH, 4);

    gemm1_u<true><<<dim3(HEXP / BN, NTOK / BM, NEXP), NTHREADS>>>(x, W1, W3, g_hid_r, HEXP, 3);
    gemm2_u<true><<<dim3(DMODEL / BN, NTOK / BM, NEXP), NTHREADS>>>(g_hid_r, W2, out, HEXP, 4);
}

// round 9
// speedup vs baseline: 1.4060x; 1.4060x over previous
#include <cuda_runtime.h>
#include <cstdint>

#define NTOK   4096
#define DMODEL 1024
#define NEXP   8
#define TOPK   2
#define HEXP   704
#define HSH    1408

#define BK 16
#define NTHREADS 256

// ---------------- scratch (device globals; no allocation allowed) ----------
__device__ int   g_cnt[NEXP];
__device__ int   g_off[NEXP + 1];
__device__ int   g_cur[NEXP];
__device__ int   g_topi[NTOK * TOPK];
__device__ float g_topw[NTOK * TOPK];
__device__ int   g_tok[NTOK * TOPK];
__device__ float g_gate[NTOK * TOPK];
__device__ float g_hid_r[NTOK * TOPK * HEXP];   // routed SwiGLU hidden
__device__ float g_hid_s[NTOK * HSH];           // shared-expert hidden

// ---------------- tiny setup kernels ---------------------------------------
__global__ void zero_kernel() {
    int t = threadIdx.x;
    if (t < NEXP) { g_cnt[t] = 0; g_cur[t] = 0; }
}

__global__ void scan_kernel() {
    int acc = 0;
    g_off[0] = 0;
    for (int e = 0; e < NEXP; e++) { acc += g_cnt[e]; g_off[e + 1] = acc; }
}

__global__ void router_kernel(const float* __restrict__ x,
                              const float* __restrict__ Wg) {
    int gw   = (blockIdx.x * blockDim.x + threadIdx.x) >> 5;
    int lane = threadIdx.x & 31;
    if (gw >= NTOK) return;
    const float* xr = x + (size_t)gw * DMODEL;

    float acc[NEXP];
#pragma unroll
    for (int e = 0; e < NEXP; e++) acc[e] = 0.f;
    for (int k = lane; k < DMODEL; k += 32) {
        float xv = xr[k];
#pragma unroll
        for (int e = 0; e < NEXP; e++) acc[e] += xv * Wg[e * DMODEL + k];
    }
#pragma unroll
    for (int e = 0; e < NEXP; e++) {
#pragma unroll
        for (int o = 16; o > 0; o >>= 1)
            acc[e] += __shfl_xor_sync(0xffffffffu, acc[e], o);
    }
    if (lane == 0) {
        float m = acc[0];
#pragma unroll
        for (int e = 1; e < NEXP; e++) m = fmaxf(m, acc[e]);
        float p[NEXP], s = 0.f;
#pragma unroll
        for (int e = 0; e < NEXP; e++) { p[e] = expf(acc[e] - m); s += p[e]; }
        float inv = 1.f / s;
#pragma unroll
        for (int e = 0; e < NEXP; e++) p[e] *= inv;

        int i0 = 0; float v0 = p[0];
#pragma unroll
        for (int e = 1; e < NEXP; e++) if (p[e] > v0) { v0 = p[e]; i0 = e; }
        int i1 = (i0 == 0) ? 1 : 0; float v1 = p[i1];
#pragma unroll
        for (int e = 0; e < NEXP; e++)
            if (e != i0 && p[e] > v1) { v1 = p[e]; i1 = e; }

        float sw = v0 + v1 + 1e-20f;
        g_topi[gw * 2] = i0;  g_topi[gw * 2 + 1] = i1;
        g_topw[gw * 2] = v0 / sw;  g_topw[gw * 2 + 1] = v1 / sw;
        atomicAdd(&g_cnt[i0], 1);
        atomicAdd(&g_cnt[i1], 1);
    }
}

__global__ void fill_kernel() {
    int n = blockIdx.x * blockDim.x + threadIdx.x;
    if (n >= NTOK) return;
#pragma unroll
    for (int s = 0; s < TOPK; s++) {
        int e   = g_topi[n * 2 + s];
        int pos = atomicAdd(&g_cur[e], 1);
        int idx = g_off[e] + pos;
        g_tok[idx]  = n;
        g_gate[idx] = g_topw[n * 2 + s];
    }
}

__device__ __forceinline__ float silu_f(float z) {
    return z / (1.f + __expf(-z));
}

// ============ GEMM1: hid = silu(A@W1)*(A@W3). CTA 128x64, tile 8x(4+4) =====
// 256 thr = 16(ty) x 16(tx); thread: rows ty*8+0..7, cols tx*4+0..3 / matrix.
template<bool ROUTED>
__global__ __launch_bounds__(NTHREADS)
void gemm1_t(const float* __restrict__ x,
             const float* __restrict__ W1g,
             const float* __restrict__ W3g,
             float* __restrict__ hid, int H) {
    int e = 0, base = 0, ne = NTOK;
    if (ROUTED) { e = blockIdx.z; base = g_off[e]; ne = g_off[e + 1] - base; }
    int m0 = blockIdx.y * 128;
    if (m0 >= ne) return;
    int n0 = blockIdx.x * 64;

    __shared__ float As[BK][132];
    __shared__ float Bs1[BK][64];
    __shared__ float Bs3[BK][64];
    __shared__ int   stok[128];

    int tid = threadIdx.x;
    if (tid < 128)
        stok[tid] = ROUTED ? ((m0 + tid < ne) ? g_tok[base + m0 + tid] : -1)
                           : (m0 + tid);
    __syncthreads();

    const float* W1 = W1g + (ROUTED ? (size_t)e * DMODEL * H : 0) + n0;
    const float* W3 = W3g + (ROUTED ? (size_t)e * DMODEL * H : 0) + n0;

    // A loader: row = tid>>1, k-octet = (tid&1)*8 (2 float4)
    int ar = tid >> 1, ac = (tid & 1) * 8;
    int tk = stok[ar];
    bool aok = (tk >= 0);
    const float* Arow = x + (size_t)(aok ? tk : 0) * DMODEL;
    // B loader: k = tid>>4, n-quad = (tid&15)*4 (1 float4 per matrix)
    int br = tid >> 4, bc = (tid & 15) * 4;

    float4 av0 = make_float4(0, 0, 0, 0), av1 = make_float4(0, 0, 0, 0);
    if (aok) {
        av0 = *(const float4*)(Arow + ac);
        av1 = *(const float4*)(Arow + ac + 4);
    }
    float4 b1v = *(const float4*)(W1 + (size_t)br * H + bc);
    float4 b3v = *(const float4*)(W3 + (size_t)br * H + bc);

    int ty = tid >> 4, tx = tid & 15;
    float acc1[8][4] = {}, acc3[8][4] = {};

    for (int kk = 0; kk < DMODEL; kk += BK) {
        As[ac + 0][ar] = av0.x; As[ac + 1][ar] = av0.y;
        As[ac + 2][ar] = av0.z; As[ac + 3][ar] = av0.w;
        As[ac + 4][ar] = av1.x; As[ac + 5][ar] = av1.y;
        As[ac + 6][ar] = av1.z; As[ac + 7][ar] = av1.w;
        *(float4*)&Bs1[br][bc] = b1v;
        *(float4*)&Bs3[br][bc] = b3v;
        __syncthreads();

        int kn = kk + BK;
        if (kn < DMODEL) {
            if (aok) {
                av0 = *(const float4*)(Arow + kn + ac);
                av1 = *(const float4*)(Arow + kn + ac + 4);
            }
            b1v = *(const float4*)(W1 + (size_t)(kn + br) * H + bc);
            b3v = *(const float4*)(W3 + (size_t)(kn + br) * H + bc);
        }

#pragma unroll
        for (int k = 0; k < BK; k++) {
            float4 a0 = *(const float4*)&As[k][ty * 8];
            float4 a1 = *(const float4*)&As[k][ty * 8 + 4];
            float4 p  = *(const float4*)&Bs1[k][tx * 4];
            float4 q  = *(const float4*)&Bs3[k][tx * 4];
            float aa[8] = { a0.x, a0.y, a0.z, a0.w, a1.x, a1.y, a1.z, a1.w };
            float pp[4] = { p.x, p.y, p.z, p.w };
            float qq[4] = { q.x, q.y, q.z, q.w };
#pragma unroll
            for (int i = 0; i < 8; i++)
#pragma unroll
                for (int j = 0; j < 4; j++) {
                    acc1[i][j] = fmaf(aa[i], pp[j], acc1[i][j]);
                    acc3[i][j] = fmaf(aa[i], qq[j], acc3[i][j]);
                }
        }
        __syncthreads();
    }

#pragma unroll
    for (int i = 0; i < 8; i++) {
        int r = ty * 8 + i;
        if (!ROUTED || (m0 + r < ne)) {
            float4 hv;
            hv.x = silu_f(acc1[i][0]) * acc3[i][0];
            hv.y = silu_f(acc1[i][1]) * acc3[i][1];
            hv.z = silu_f(acc1[i][2]) * acc3[i][2];
            hv.w = silu_f(acc1[i][3]) * acc3[i][3];
            *(float4*)&hid[(size_t)(base + m0 + r) * H + n0 + tx * 4] = hv;
        }
    }
}

// ============ GEMM2: out (+)= [gate *] (hid @ W2). CTA 128x128, tile 8x8 ====
template<bool ROUTED>
__global__ __launch_bounds__(NTHREADS)
void gemm2_t(const float* __restrict__ hidg,
             const float* __restrict__ W2g,
             float* __restrict__ out, int K) {
    int e = 0, base = 0, ne = NTOK;
    if (ROUTED) { e = blockIdx.z; base = g_off[e]; ne = g_off[e + 1] - base; }
    int m0 = blockIdx.y * 128;
    if (m0 >= ne) return;
    int n0 = blockIdx.x * 128;

    __shared__ float As[BK][132];
    __shared__ float Bs[BK][128];
    __shared__ int   stok[128];
    __shared__ float sgate[128];

    int tid = threadIdx.x;
    if (ROUTED) {
        if (tid < 128) {
            bool v = (m0 + tid < ne);
            stok[tid]  = v ? g_tok[base + m0 + tid] : 0;
            sgate[tid] = v ? g_gate[base + m0 + tid] : 0.f;
        }
        __syncthreads();
    }

    const float* Bp = W2g + (ROUTED ? (size_t)e * K * DMODEL : 0) + n0;

    int ar = tid >> 1, ac = (tid & 1) * 8;
    bool aok = (m0 + ar < ne);
    const float* Arow = hidg + (size_t)(base + m0 + (aok ? ar : 0)) * K;
    int br = tid >> 4, bc = (tid & 15) * 4;

    float4 av0 = make_float4(0, 0, 0, 0), av1 = make_float4(0, 0, 0, 0);
    if (aok) {
        av0 = *(const float4*)(Arow + ac);
        av1 = *(const float4*)(Arow + ac + 4);
    }
    float4 bv0 = *(const float4*)(Bp + (size_t)br * DMODEL + bc);
    float4 bv1 = *(const float4*)(Bp + (size_t)br * DMODEL + bc + 64);

    int ty = tid >> 4, tx = tid & 15;
    float acc[8][8] = {};

    for (int kk = 0; kk < K; kk += BK) {
        As[ac + 0][ar] = av0.x; As[ac + 1][ar] = av0.y;
        As[ac + 2][ar] = av0.z; As[ac + 3][ar] = av0.w;
        As[ac + 4][ar] = av1.x; As[ac + 5][ar] = av1.y;
        As[ac + 6][ar] = av1.z; As[ac + 7][ar] = av1.w;
        *(float4*)&Bs[br][bc]      = bv0;
        *(float4*)&Bs[br][bc + 64] = bv1;
        __syncthreads();

        int kn = kk + BK;
        if (kn < K) {
            if (aok) {
                av0 = *(const float4*)(Arow + kn + ac);
                av1 = *(const float4*)(Arow + kn + ac + 4);
            }
            bv0 = *(const float4*)(Bp + (size_t)(kn + br) * DMODEL + bc);
            bv1 = *(const float4*)(Bp + (size_t)(kn + br) * DMODEL + bc + 64);
        }

#pragma unroll
        for (int k = 0; k < BK; k++) {
            float4 a0 = *(const float4*)&As[k][ty * 8];
            float4 a1 = *(const float4*)&As[k][ty * 8 + 4];
            float4 b0 = *(const float4*)&Bs[k][tx * 8];
            float4 b1 = *(const float4*)&Bs[k][tx * 8 + 4];
            float aa[8] = { a0.x, a0.y, a0.z, a0.w, a1.x, a1.y, a1.z, a1.w };
            float bb[8] = { b0.x, b0.y, b0.z, b0.w, b1.x, b1.y, b1.z, b1.w };
#pragma unroll
            for (int i = 0; i < 8; i++)
#pragma unroll
                for (int j = 0; j < 8; j++)
                    acc[i][j] = fmaf(aa[i], bb[j], acc[i][j]);
        }
        __syncthreads();
    }

#pragma unroll
    for (int i = 0; i < 8; i++) {
        int r = ty * 8 + i;
        if (ROUTED) {
            if (m0 + r < ne) {
                int   tk = stok[r];
                float w  = sgate[r];
                float* op = out + (size_t)tk * DMODEL + n0 + tx * 8;
#pragma unroll
                for (int j = 0; j < 8; j++)
                    atomicAdd(op + j, w * acc[i][j]);
            }
        } else {
            float* op = out + (size_t)(m0 + r) * DMODEL + n0 + tx * 8;
            float4 v0 = make_float4(acc[i][0], acc[i][1], acc[i][2], acc[i][3]);
            float4 v1 = make_float4(acc[i][4], acc[i][5], acc[i][6], acc[i][7]);
            *(float4*)op       = v0;
            *(float4*)(op + 4) = v1;
        }
    }
}

// ---------------- launch -----------------------------------------------------
extern "C" void kernel_launch(void* const* d_in, const int* in_sizes, int n_in,
                              void* d_out, int out_size) {
    const float* x   = (const float*)d_in[0];
    const float* Wg  = (const float*)d_in[1];
    const float* W1  = (const float*)d_in[2];
    const float* W3  = (const float*)d_in[3];
    const float* W2  = (const float*)d_in[4];
    const float* Ws1 = (const float*)d_in[5];
    const float* Ws3 = (const float*)d_in[6];
    const float* Ws2 = (const float*)d_in[7];
    float* out = (float*)d_out;

    zero_kernel<<<1, 32>>>();
    router_kernel<<<NTOK / 8, 256>>>(x, Wg);
    scan_kernel<<<1, 1>>>();
    fill_kernel<<<NTOK / 256, 256>>>();

    // shared expert (writes every element of out) must precede routed scatter
    gemm1_t<false><<<dim3(HSH / 64, NTOK / 128), NTHREADS>>>(x, Ws1, Ws3, g_hid_s, HSH);
    gemm2_t<false><<<dim3(DMODEL / 128, NTOK / 128), NTHREADS>>>(g_hid_s, Ws2, out, HSH);

    gemm1_t<true><<<dim3(HEXP / 64, NTOK / 128, NEXP), NTHREADS>>>(x, W1, W3, g_hid_r, HEXP);
    gemm2_t<true><<<dim3(DMODEL / 128, NTOK / 128, NEXP), NTHREADS>>>(g_hid_r, W2, out, HEXP);
}

// round 10
// speedup vs baseline: 2.6806x; 1.9066x over previous
#include <cuda_runtime.h>
#include <cstdint>

#define NTOK   4096
#define DMODEL 1024
#define NEXP   8
#define TOPK   2
#define HEXP   704
#define HSH    1408
#define BK     16

// ---------------- scratch (device globals; no allocation allowed) ----------
__device__ int   g_cnt[NEXP];
__device__ int   g_off[NEXP + 1];
__device__ int   g_cur[NEXP];
__device__ int   g_topi[NTOK * TOPK];
__device__ float g_topw[NTOK * TOPK];
__device__ int   g_tok[NTOK * TOPK];
__device__ float g_gate[NTOK * TOPK];
__device__ float g_hid_r[NTOK * TOPK * HEXP];   // routed SwiGLU hidden
__device__ float g_hid_s[NTOK * HSH];           // shared-expert hidden

// ---------------- tiny setup kernels ---------------------------------------
__global__ void zero_kernel() {
    int t = threadIdx.x;
    if (t < NEXP) { g_cnt[t] = 0; g_cur[t] = 0; }
}

__global__ void scan_kernel() {
    int acc = 0;
    g_off[0] = 0;
    for (int e = 0; e < NEXP; e++) { acc += g_cnt[e]; g_off[e + 1] = acc; }
}

__global__ void zero_out_kernel(float* __restrict__ out) {
    size_t i = ((size_t)blockIdx.x * blockDim.x + threadIdx.x) * 4;
    *(float4*)(out + i) = make_float4(0.f, 0.f, 0.f, 0.f);
}

__global__ void router_kernel(const float* __restrict__ x,
                              const float* __restrict__ Wg) {
    int gw   = (blockIdx.x * blockDim.x + threadIdx.x) >> 5;
    int lane = threadIdx.x & 31;
    if (gw >= NTOK) return;
    const float* xr = x + (size_t)gw * DMODEL;

    float acc[NEXP];
#pragma unroll
    for (int e = 0; e < NEXP; e++) acc[e] = 0.f;
    for (int k = lane; k < DMODEL; k += 32) {
        float xv = xr[k];
#pragma unroll
        for (int e = 0; e < NEXP; e++) acc[e] += xv * Wg[e * DMODEL + k];
    }
#pragma unroll
    for (int e = 0; e < NEXP; e++) {
#pragma unroll
        for (int o = 16; o > 0; o >>= 1)
            acc[e] += __shfl_xor_sync(0xffffffffu, acc[e], o);
    }
    if (lane == 0) {
        float m = acc[0];
#pragma unroll
        for (int e = 1; e < NEXP; e++) m = fmaxf(m, acc[e]);
        float p[NEXP], s = 0.f;
#pragma unroll
        for (int e = 0; e < NEXP; e++) { p[e] = expf(acc[e] - m); s += p[e]; }
        float inv = 1.f / s;
#pragma unroll
        for (int e = 0; e < NEXP; e++) p[e] *= inv;

        int i0 = 0; float v0 = p[0];
#pragma unroll
        for (int e = 1; e < NEXP; e++) if (p[e] > v0) { v0 = p[e]; i0 = e; }
        int i1 = (i0 == 0) ? 1 : 0; float v1 = p[i1];
#pragma unroll
        for (int e = 0; e < NEXP; e++)
            if (e != i0 && p[e] > v1) { v1 = p[e]; i1 = e; }

        float sw = v0 + v1 + 1e-20f;
        g_topi[gw * 2] = i0;  g_topi[gw * 2 + 1] = i1;
        g_topw[gw * 2] = v0 / sw;  g_topw[gw * 2 + 1] = v1 / sw;
        atomicAdd(&g_cnt[i0], 1);
        atomicAdd(&g_cnt[i1], 1);
    }
}

__global__ void fill_kernel() {
    int n = blockIdx.x * blockDim.x + threadIdx.x;
    if (n >= NTOK) return;
#pragma unroll
    for (int s = 0; s < TOPK; s++) {
        int e   = g_topi[n * 2 + s];
        int pos = atomicAdd(&g_cur[e], 1);
        int idx = g_off[e] + pos;
        g_tok[idx]  = n;
        g_gate[idx] = g_topw[n * 2 + s];
    }
}

__device__ __forceinline__ float silu_f(float z) {
    return z / (1.f + __expf(-z));
}

// ============ GEMM1 fused: hid = silu(A@W1)*(A@W3) ==========================
// grid (11, 64, 10): z<8 routed expert z; z=8,9 shared-expert column halves.
// CTA 64x64, thread tile 4x4 per matrix, double-buffered smem (1 sync/tile).
__global__ __launch_bounds__(256)
void gemm1_all(const float* __restrict__ x,
               const float* __restrict__ W1,
               const float* __restrict__ W3,
               const float* __restrict__ Ws1,
               const float* __restrict__ Ws3) {
    int z = blockIdx.z;
    bool routed = (z < NEXP);
    int base = 0, ne = NTOK, H, n0;
    const float *B1, *B3;
    float* hid;
    if (routed) {
        base = g_off[z]; ne = g_off[z + 1] - base;
        H = HEXP; hid = g_hid_r;
        n0 = blockIdx.x * 64;
        B1 = W1 + (size_t)z * DMODEL * HEXP + n0;
        B3 = W3 + (size_t)z * DMODEL * HEXP + n0;
    } else {
        H = HSH; hid = g_hid_s;
        n0 = (blockIdx.x + (z - NEXP) * 11) * 64;
        B1 = Ws1 + n0;
        B3 = Ws3 + n0;
    }
    int m0 = blockIdx.y * 64;
    if (m0 >= ne) return;

    __shared__ float As[2][BK][68];
    __shared__ float Bs1[2][BK][64];
    __shared__ float Bs3[2][BK][64];
    __shared__ int   stok[64];

    int tid = threadIdx.x;
    if (tid < 64)
        stok[tid] = routed ? ((m0 + tid < ne) ? g_tok[base + m0 + tid] : -1)
                           : (m0 + tid);
    __syncthreads();

    int ar = tid >> 2, ac = (tid & 3) * 4;
    int tk = stok[ar];
    bool aok = (tk >= 0);
    const float* Arow = x + (size_t)(aok ? tk : 0) * DMODEL;
    int br = tid >> 4, bc = (tid & 15) * 4;

    float4 av  = aok ? *(const float4*)(Arow + ac) : make_float4(0, 0, 0, 0);
    float4 b1v = *(const float4*)(B1 + (size_t)br * H + bc);
    float4 b3v = *(const float4*)(B3 + (size_t)br * H + bc);

    // prologue: stage tile 0 into buffer 0
    As[0][ac + 0][ar] = av.x; As[0][ac + 1][ar] = av.y;
    As[0][ac + 2][ar] = av.z; As[0][ac + 3][ar] = av.w;
    *(float4*)&Bs1[0][br][bc] = b1v;
    *(float4*)&Bs3[0][br][bc] = b3v;
    __syncthreads();

    int tm0 = (tid >> 4) * 4, tn0 = (tid & 15) * 4;
    float acc1[4][4] = {}, acc3[4][4] = {};

    const int NT = DMODEL / BK;
    for (int t = 0; t < NT; t++) {
        int buf = t & 1;
        int kn  = (t + 1) * BK;
        if (kn < DMODEL) {
            if (aok) av = *(const float4*)(Arow + kn + ac);
            b1v = *(const float4*)(B1 + (size_t)(kn + br) * H + bc);
            b3v = *(const float4*)(B3 + (size_t)(kn + br) * H + bc);
        }
#pragma unroll
        for (int k = 0; k < BK; k++) {
            float4 a  = *(const float4*)&As[buf][k][tm0];
            float4 b1 = *(const float4*)&Bs1[buf][k][tn0];
            float4 b3 = *(const float4*)&Bs3[buf][k][tn0];
            float aa[4]  = { a.x, a.y, a.z, a.w };
            float bb1[4] = { b1.x, b1.y, b1.z, b1.w };
            float bb3[4] = { b3.x, b3.y, b3.z, b3.w };
#pragma unroll
            for (int i = 0; i < 4; i++)
#pragma unroll
                for (int j = 0; j < 4; j++) {
                    acc1[i][j] = fmaf(aa[i], bb1[j], acc1[i][j]);
                    acc3[i][j] = fmaf(aa[i], bb3[j], acc3[i][j]);
                }
        }
        if (kn < DMODEL) {
            int nb = buf ^ 1;
            As[nb][ac + 0][ar] = av.x; As[nb][ac + 1][ar] = av.y;
            As[nb][ac + 2][ar] = av.z; As[nb][ac + 3][ar] = av.w;
            *(float4*)&Bs1[nb][br][bc] = b1v;
            *(float4*)&Bs3[nb][br][bc] = b3v;
        }
        __syncthreads();
    }

#pragma unroll
    for (int i = 0; i < 4; i++) {
        int r = tm0 + i;
        if (m0 + r < ne) {
            float4 hv;
            hv.x = silu_f(acc1[i][0]) * acc3[i][0];
            hv.y = silu_f(acc1[i][1]) * acc3[i][1];
            hv.z = silu_f(acc1[i][2]) * acc3[i][2];
            hv.w = silu_f(acc1[i][3]) * acc3[i][3];
            *(float4*)&hid[(size_t)(base + m0 + r) * H + n0 + tn0] = hv;
        }
    }
}

// ============ GEMM2 fused: out += w * (hid @ W2) ============================
// grid (16, 64, 9): z<8 routed expert z (gate weight); z=8 shared (w=1).
// out pre-zeroed; all paths use atomicAdd so no cross-z ordering needed.
__global__ __launch_bounds__(256)
void gemm2_all(const float* __restrict__ W2,
               const float* __restrict__ Ws2,
               float* __restrict__ out) {
    int z = blockIdx.z;
    bool routed = (z < NEXP);
    int base = 0, ne = NTOK, K;
    const float* Bp;
    const float* hidg;
    int n0 = blockIdx.x * 64;
    if (routed) {
        base = g_off[z]; ne = g_off[z + 1] - base;
        K = HEXP; hidg = g_hid_r;
        Bp = W2 + (size_t)z * HEXP * DMODEL + n0;
    } else {
        K = HSH; hidg = g_hid_s;
        Bp = Ws2 + n0;
    }
    int m0 = blockIdx.y * 64;
    if (m0 >= ne) return;

    __shared__ float As[2][BK][68];
    __shared__ float Bs[2][BK][64];
    __shared__ int   stok[64];
    __shared__ float sgate[64];

    int tid = threadIdx.x;
    if (tid < 64) {
        if (routed) {
            bool v = (m0 + tid < ne);
            stok[tid]  = v ? g_tok[base + m0 + tid] : 0;
            sgate[tid] = v ? g_gate[base + m0 + tid] : 0.f;
        } else {
            stok[tid]  = m0 + tid;
            sgate[tid] = 1.f;
        }
    }
    __syncthreads();

    int ar = tid >> 2, ac = (tid & 3) * 4;
    bool aok = (m0 + ar < ne);
    const float* Arow = hidg + (size_t)(base + m0 + (aok ? ar : 0)) * K;
    int br = tid >> 4, bc = (tid & 15) * 4;

    float4 av = aok ? *(const float4*)(Arow + ac) : make_float4(0, 0, 0, 0);
    float4 bv = *(const float4*)(Bp + (size_t)br * DMODEL + bc);

    As[0][ac + 0][ar] = av.x; As[0][ac + 1][ar] = av.y;
    As[0][ac + 2][ar] = av.z; As[0][ac + 3][ar] = av.w;
    *(float4*)&Bs[0][br][bc] = bv;
    __syncthreads();

    int tm0 = (tid >> 4) * 4, tn0 = (tid & 15) * 4;
    float acc[4][4] = {};

    const int NT_ = K / BK;
    for (int t = 0; t < NT_; t++) {
        int buf = t & 1;
        int kn  = (t + 1) * BK;
        if (kn < K) {
            if (aok) av = *(const float4*)(Arow + kn + ac);
            bv = *(const float4*)(Bp + (size_t)(kn + br) * DMODEL + bc);
        }
#pragma unroll
        for (int k = 0; k < BK; k++) {
            float4 a = *(const float4*)&As[buf][k][tm0];
            float4 b = *(const float4*)&Bs[buf][k][tn0];
            float aa[4] = { a.x, a.y, a.z, a.w };
            float bb[4] = { b.x, b.y, b.z, b.w };
#pragma unroll
            for (int i = 0; i < 4; i++)
#pragma unroll
                for (int j = 0; j < 4; j++)
                    acc[i][j] = fmaf(aa[i], bb[j], acc[i][j]);
        }
        if (kn < K) {
            int nb = buf ^ 1;
            As[nb][ac + 0][ar] = av.x; As[nb][ac + 1][ar] = av.y;
            As[nb][ac + 2][ar] = av.z; As[nb][ac + 3][ar] = av.w;
            *(float4*)&Bs[nb][br][bc] = bv;
        }
        __syncthreads();
    }

#pragma unroll
    for (int i = 0; i < 4; i++) {
        int r = tm0 + i;
        if (m0 + r < ne) {
            int   tk = stok[r];
            float w  = sgate[r];
            float* op = out + (size_t)tk * DMODEL + n0 + tn0;
            atomicAdd(op + 0, w * acc[i][0]);
            atomicAdd(op + 1, w * acc[i][1]);
            atomicAdd(op + 2, w * acc[i][2]);
            atomicAdd(op + 3, w * acc[i][3]);
        }
    }
}

// ---------------- launch -----------------------------------------------------
extern "C" void kernel_launch(void* const* d_in, const int* in_sizes, int n_in,
                              void* d_out, int out_size) {
    const float* x   = (const float*)d_in[0];
    const float* Wg  = (const float*)d_in[1];
    const float* W1  = (const float*)d_in[2];
    const float* W3  = (const float*)d_in[3];
    const float* W2  = (const float*)d_in[4];
    const float* Ws1 = (const float*)d_in[5];
    const float* Ws3 = (const float*)d_in[6];
    const float* Ws2 = (const float*)d_in[7];
    float* out = (float*)d_out;

    zero_kernel<<<1, 32>>>();
    router_kernel<<<NTOK / 8, 256>>>(x, Wg);
    scan_kernel<<<1, 1>>>();
    fill_kernel<<<NTOK / 256, 256>>>();
    zero_out_kernel<<<(NTOK * DMODEL) / 1024, 256>>>(out);

    // fused up-proj: routed (z=0..7) + shared halves (z=8,9)
    gemm1_all<<<dim3(HEXP / 64, NTOK / 64, 10), 256>>>(x, W1, W3, Ws1, Ws3);
    // fused down-proj: routed (z=0..7) + shared (z=8), all atomic into out
    gemm2_all<<<dim3(DMODEL / 64, NTOK / 64, 9), 256>>>(W2, Ws2, out);
}